// round 13
// baseline (speedup 1.0000x reference)
#include <cuda_runtime.h>
#include <math_constants.h>
#include <stdint.h>

#define N_BINS     15
#define C_DIM      100
#define VPR        25          // float4 vectors per row
#define FULL       0xffffffffu
#define THREADS    256
#define BLOCKS     2368        // 8 blocks/SM
#define MACRO_ROWS 256         // rows per block macro-tile

// Persistent accumulators. Zero at module load; the LAST block of every
// launch resets them after consuming -> deterministic across graph replays.
__device__ float    g_cnt[N_BINS];
__device__ double   g_conf[N_BINS];
__device__ float    g_accs[N_BINS];
__device__ unsigned g_ctr;

__global__ void __launch_bounds__(THREADS) ece_fused_kernel(
    const float* __restrict__ logits,
    const char*  __restrict__ labels_raw,
    float* __restrict__ out,
    int n, int vec_ok, float inv_n)
{
    __shared__ float s_max[MACRO_ROWS * VPR];   // 25.6 KB: per-float4 maxima
    __shared__ float s_cnt[N_BINS], s_conf[N_BINS], s_acc[N_BINS];
    __shared__ int   s_lstride;
    __shared__ unsigned s_ticket;

    const int tid  = threadIdx.x;
    const int lane = tid & 31;

    if (tid < N_BINS) { s_cnt[tid] = 0.f; s_conf[tid] = 0.f; s_acc[tid] = 0.f; }

    // Label dtype detect: odd int32 words all zero => int64 (little-endian).
    // Either way the value is the 32-bit word at row*lstride.
    if (tid < 32) {
        int idx = 1 + 2 * tid;
        int v = (idx < n) ? ((const int*)labels_raw)[idx] : 0;
        unsigned any = __ballot_sync(FULL, v != 0);
        if (tid == 0) s_lstride = (any == 0) ? 8 : 4;
    }
    __syncthreads();

    const size_t lstride = (size_t)s_lstride;
    const int nmacros = (n + MACRO_ROWS - 1) / MACRO_ROWS;

    if (vec_ok) {
        for (int mb = blockIdx.x; mb < nmacros; mb += gridDim.x) {
            const int base = mb * MACRO_ROWS;
            const int rows = min(MACRO_ROWS, n - base);
            const int nvec = rows * VPR;

            // ---- Pass 1: coalesced stream, compress each float4 to its max
            const float4* __restrict__ src =
                reinterpret_cast<const float4*>(logits) + (size_t)base * VPR;
            #pragma unroll 5
            for (int i = tid; i < nvec; i += THREADS) {
                float4 v = src[i];
                s_max[i] = fmaxf(fmaxf(v.x, v.y), fmaxf(v.z, v.w));
            }
            __syncthreads();

            // ---- Pass 2: thread-per-row epilogue (32 rows / warp-instr)
            if (tid < rows) {
                const int row = base + tid;
                // issue both dependent loads early
                const int lab = *(const int*)(labels_raw + (size_t)row * lstride);
                const float vl = logits[(size_t)row * C_DIM + lab];

                // conflict-free LDS: word idx = tid*25 + j, 25 coprime 32
                const float* sm = s_max + tid * VPR;
                float m0 = sm[0],  m1 = sm[1],  m2 = sm[2],  m3 = sm[3];
                #pragma unroll
                for (int j = 4; j < 24; j += 4) {
                    m0 = fmaxf(m0, sm[j]);
                    m1 = fmaxf(m1, sm[j + 1]);
                    m2 = fmaxf(m2, sm[j + 2]);
                    m3 = fmaxf(m3, sm[j + 3]);
                }
                float m = fmaxf(fmaxf(m0, m1), fmaxf(m2, fmaxf(m3, sm[24])));

                // sigmoid monotone: conf = sigmoid(max logit)
                float conf = __fdividef(1.0f, 1.0f + __expf(-m));
                // searchsorted(linspace(0,1,16), conf, 'left') - 1, clipped
                int bin = __float2int_ru(conf * 15.0f) - 1;
                bin = bin < 0 ? 0 : (bin > N_BINS - 1 ? N_BINS - 1 : bin);

                atomicAdd(&s_cnt[bin], 1.0f);
                atomicAdd(&s_conf[bin], conf);
                if (vl == m) atomicAdd(&s_acc[bin], 1.0f);
            }
            __syncthreads();   // protect s_max before next macro
        }
    } else {
        // scalar fallback (unaligned logits base): warp-per-row
        const int warp   = (int)((blockIdx.x * THREADS + tid) >> 5);
        const int nwarps = (BLOCKS * THREADS) >> 5;
        for (int row = warp; row < n; row += nwarps) {
            float m = -CUDART_INF_F;
            float vl = 0.0f;
            int lab = *(const int*)(labels_raw + (size_t)row * lstride);
            #pragma unroll
            for (int j = 0; j < 4; j++) {
                int c = lane + j * 32;
                if (c < C_DIM) {
                    float x = logits[(size_t)row * C_DIM + c];
                    m = fmaxf(m, x);
                    if (c == lab) vl = x;
                }
            }
            // warp max via shfl tree
            #pragma unroll
            for (int off = 16; off > 0; off >>= 1)
                m = fmaxf(m, __shfl_xor_sync(FULL, m, off));
            unsigned win = __ballot_sync(FULL,
                (lane == (lab & 31)) && (vl == m));
            if (lane == 0) {
                float conf = __fdividef(1.0f, 1.0f + __expf(-m));
                int bin = __float2int_ru(conf * 15.0f) - 1;
                bin = bin < 0 ? 0 : (bin > N_BINS - 1 ? N_BINS - 1 : bin);
                atomicAdd(&s_cnt[bin], 1.0f);
                atomicAdd(&s_conf[bin], conf);
                if (win) atomicAdd(&s_acc[bin], 1.0f);
            }
        }
    }

    // ---- block hist -> global ----
    __syncthreads();
    if (tid < N_BINS) {
        float c = s_cnt[tid];
        if (c != 0.0f) {
            atomicAdd(&g_cnt[tid],  c);
            atomicAdd(&g_conf[tid], (double)s_conf[tid]);
            atomicAdd(&g_accs[tid], s_acc[tid]);
        }
    }

    // ticket: last block finalizes and resets persistent state
    __threadfence();
    if (tid == 0) s_ticket = atomicAdd(&g_ctr, 1u);
    __syncthreads();
    if (s_ticket == (unsigned)(gridDim.x - 1) && tid == 0) {
        __threadfence();
        float ece = 0.0f;
        #pragma unroll
        for (int b = 0; b < N_BINS; b++) {
            float cnt = g_cnt[b];
            if (cnt > 0.0f) {
                float avg_conf = (float)g_conf[b] / cnt;
                float avg_acc  = g_accs[b] / cnt;
                ece += (avg_conf - avg_acc) * (cnt * inv_n);
            }
            g_cnt[b] = 0.0f; g_conf[b] = 0.0; g_accs[b] = 0.0f;
        }
        out[0] = ece;
        g_ctr = 0u;
        __threadfence();
    }
}

extern "C" void kernel_launch(void* const* d_in, const int* in_sizes, int n_in,
                              void* d_out, int out_size) {
    // Resolve input order by element count (logits = C_DIM x labels count).
    long long s0 = in_sizes[0], s1 = in_sizes[1];
    int logits_idx = (s0 > s1) ? 0 : 1;
    int labels_idx = 1 - logits_idx;

    const float* logits     = (const float*)d_in[logits_idx];
    const char*  labels_raw = (const char*)d_in[labels_idx];
    int n = (int)((s0 < s1) ? s0 : s1);
    float* out = (float*)d_out;

    int vec_ok = ((uintptr_t)logits & 15) == 0 ? 1 : 0;

    ece_fused_kernel<<<BLOCKS, THREADS>>>(logits, labels_raw, out, n, vec_ok,
                                          1.0f / (float)n);
}

// round 14
// speedup vs baseline: 1.0724x; 1.0724x over previous
#include <cuda_runtime.h>
#include <math_constants.h>
#include <stdint.h>

#define N_BINS  15
#define C_DIM   100
#define FULL    0xffffffffu
#define THREADS 256
#define BLOCKS  1036                 // 7 blocks/SM x 148 SMs: one clean wave
#define NWARPS  ((BLOCKS * THREADS) >> 5)   // 8288

// Persistent accumulators. Zero at module load; the LAST block of every
// launch resets them after consuming -> deterministic across graph replays.
__device__ float    g_cnt[N_BINS];
__device__ double   g_conf[N_BINS];
__device__ float    g_accs[N_BINS];
__device__ unsigned g_ctr;

// Order-preserving float -> u32 map (u32 compare == float compare) + inverse.
__device__ __forceinline__ unsigned fmap(float f) {
    unsigned b = __float_as_uint(f);
    return ((int)b >= 0) ? (b | 0x80000000u) : ~b;
}
__device__ __forceinline__ float funmap(unsigned u) {
    unsigned b = (u & 0x80000000u) ? (u & 0x7fffffffu) : ~u;
    return __uint_as_float(b);
}

__global__ void __launch_bounds__(THREADS) ece_fused_kernel(
    const float* __restrict__ logits,
    const char*  __restrict__ labels_raw,
    float* __restrict__ out,
    int n, int vec_ok, float inv_n)
{
    __shared__ int   s_cnt_acc[N_BINS];   // cnt<<16 | acc (block totals fit)
    __shared__ float s_conf[N_BINS];
    __shared__ int   s_lstride;
    __shared__ unsigned s_ticket;

    const int tid  = threadIdx.x;
    const int lane = tid & 31;

    if (tid < N_BINS) { s_cnt_acc[tid] = 0; s_conf[tid] = 0.f; }

    // Label dtype detect: odd int32 words all zero => int64 (little-endian).
    if (tid < 32) {
        int idx = 1 + 2 * tid;
        int v = (idx < n) ? ((const int*)labels_raw)[idx] : 0;
        unsigned any = __ballot_sync(FULL, v != 0);
        if (tid == 0) s_lstride = (any == 0) ? 8 : 4;
    }
    __syncthreads();

    const int lstride = s_lstride;
    const int warp    = (int)((blockIdx.x * THREADS + tid) >> 5);

    if (vec_ok && warp < n) {
        const int lcl = lane < 25 ? lane : 24;     // clamp: dup loads coalesce
        const float4* __restrict__ p =
            reinterpret_cast<const float4*>(logits) + (size_t)warp * 25 + lcl;
        const char* __restrict__ lp = labels_raw + (size_t)warp * lstride;
        const size_t pstride = (size_t)NWARPS * 25;
        const int    lstep   = NWARPS * lstride;

        const int nrows = (n - 1 - warp) / NWARPS + 1;

        float4 v   = *p;
        int    lab = *(const int*)lp;

        unsigned mymax = 0u;        // batch slot registers (lane k owns row k)
        int      mylab = 0;
        int done = 0;
        int rowb = warp;            // first row of current batch

        while (done < nrows) {
            const int bcnt = min(32, nrows - done);

            #pragma unroll 4
            for (int k = 0; k < bcnt; k++) {
                const bool hasnext = (done + k + 1) < nrows;
                p  += pstride;
                lp += lstep;
                float4 v2; int lab2;
                if (hasnext) { v2 = *p; lab2 = *(const int*)lp; }

                // ---- per-row: max only ----
                float m = fmaxf(fmaxf(v.x, v.y), fmaxf(v.z, v.w));
                unsigned maxu = __reduce_max_sync(FULL, fmap(m));
                if (k == lane) { mymax = maxu; mylab = lab; }

                if (hasnext) { v = v2; lab = lab2; }
            }

            // ---- batched epilogue: lane k resolves row k (thread-parallel)
            {
                const unsigned am = (bcnt >= 32) ? FULL : ((1u << bcnt) - 1u);
                if (lane < bcnt) {
                    float mm   = funmap(mymax);
                    float conf = __fdividef(1.0f, 1.0f + __expf(-mm));
                    int bin = __float2int_ru(conf * 15.0f) - 1;
                    bin = bin < 0 ? 0 : (bin > N_BINS - 1 ? N_BINS - 1 : bin);

                    const int myrow = rowb + lane * NWARPS;
                    const float vl =
                        __ldg(logits + (size_t)myrow * C_DIM + mylab);
                    const int acc = (fmap(vl) == mymax) ? 1 : 0;

                    unsigned peers = __match_any_sync(am, bin);
                    unsigned accb  = __ballot_sync(am, acc);
                    if ((__ffs(peers) - 1) == lane) {   // one leader per bin
                        atomicAdd(&s_cnt_acc[bin],
                                  (__popc(peers) << 16) | __popc(peers & accb));
                    }
                    atomicAdd(&s_conf[bin], conf);
                }
            }

            done += bcnt;
            rowb += bcnt * NWARPS;
        }
    } else if (warp < n) {
        // scalar fallback (unaligned logits base): warp-per-row
        for (int row = warp; row < n; row += NWARPS) {
            float m = -CUDART_INF_F;
            float vl = 0.0f;
            int lab = *(const int*)(labels_raw + (size_t)row * lstride);
            #pragma unroll
            for (int j = 0; j < 4; j++) {
                int c = lane + j * 32;
                if (c < C_DIM) {
                    float x = logits[(size_t)row * C_DIM + c];
                    m = fmaxf(m, x);
                    if (c == lab) vl = x;
                }
            }
            unsigned maxu = __reduce_max_sync(FULL, fmap(m));
            float mm = funmap(maxu);
            unsigned win = __ballot_sync(FULL,
                (lane == (lab & 31)) && (vl == mm));
            if (lane == 0) {
                float conf = __fdividef(1.0f, 1.0f + __expf(-mm));
                int bin = __float2int_ru(conf * 15.0f) - 1;
                bin = bin < 0 ? 0 : (bin > N_BINS - 1 ? N_BINS - 1 : bin);
                atomicAdd(&s_cnt_acc[bin], (1 << 16) | (win ? 1 : 0));
                atomicAdd(&s_conf[bin], conf);
            }
        }
    }

    // ---- block hist -> global ----
    __syncthreads();
    if (tid < N_BINS) {
        int ca = s_cnt_acc[tid];
        if (ca != 0) {
            atomicAdd(&g_cnt[tid],  (float)(ca >> 16));
            atomicAdd(&g_accs[tid], (float)(ca & 0xffff));
            atomicAdd(&g_conf[tid], (double)s_conf[tid]);
        }
    }

    // ticket: last block finalizes and resets persistent state
    __threadfence();
    if (tid == 0) s_ticket = atomicAdd(&g_ctr, 1u);
    __syncthreads();
    if (s_ticket == (unsigned)(gridDim.x - 1) && tid == 0) {
        __threadfence();
        float ece = 0.0f;
        #pragma unroll
        for (int b = 0; b < N_BINS; b++) {
            float cnt = g_cnt[b];
            if (cnt > 0.0f) {
                float avg_conf = (float)g_conf[b] / cnt;
                float avg_acc  = g_accs[b] / cnt;
                ece += (avg_conf - avg_acc) * (cnt * inv_n);
            }
            g_cnt[b] = 0.0f; g_conf[b] = 0.0; g_accs[b] = 0.0f;
        }
        out[0] = ece;
        g_ctr = 0u;
        __threadfence();
    }
}

extern "C" void kernel_launch(void* const* d_in, const int* in_sizes, int n_in,
                              void* d_out, int out_size) {
    // Resolve input order by element count (logits = C_DIM x labels count).
    long long s0 = in_sizes[0], s1 = in_sizes[1];
    int logits_idx = (s0 > s1) ? 0 : 1;
    int labels_idx = 1 - logits_idx;

    const float* logits     = (const float*)d_in[logits_idx];
    const char*  labels_raw = (const char*)d_in[labels_idx];
    int n = (int)((s0 < s1) ? s0 : s1);
    float* out = (float*)d_out;

    int vec_ok = ((uintptr_t)logits & 15) == 0 ? 1 : 0;

    ece_fused_kernel<<<BLOCKS, THREADS>>>(logits, labels_raw, out, n, vec_ok,
                                          1.0f / (float)n);
}

// round 16
// speedup vs baseline: 1.2802x; 1.1938x over previous
#include <cuda_runtime.h>
#include <math_constants.h>
#include <stdint.h>

#define N_BINS  15
#define C_DIM   100
#define FULL    0xffffffffu
#define THREADS 256
#define BLOCKS  2368         // 8 blocks/SM target: occupancy is king

// Persistent accumulators. Zero at module load; the LAST block of every
// launch resets them after consuming -> deterministic across graph replays.
__device__ float    g_cnt[N_BINS];
__device__ double   g_conf[N_BINS];
__device__ float    g_accs[N_BINS];
__device__ unsigned g_ctr;

// Order-preserving float -> u32 map (u32 compare == float compare) + inverse.
__device__ __forceinline__ unsigned fmap(float f) {
    unsigned b = __float_as_uint(f);
    return ((int)b >= 0) ? (b | 0x80000000u) : ~b;
}
__device__ __forceinline__ float funmap(unsigned u) {
    unsigned b = (u & 0x80000000u) ? (u & 0x7fffffffu) : ~u;
    return __uint_as_float(b);
}

__device__ __forceinline__ void ece_row(
    const float4 v, const int lab, const int lane,
    float& r_cnt, float& r_conf, float& r_acc)
{
    float m = fmaxf(fmaxf(v.x, v.y), fmaxf(v.z, v.w));
    unsigned maxu = __reduce_max_sync(FULL, fmap(m));
    float mm = funmap(maxu);                    // exact max logit

    // accuracy: does the label's position hold the max value?
    int lc = lab & 3;
    float vl = (lc == 0) ? v.x : (lc == 1) ? v.y : (lc == 2) ? v.z : v.w;
    unsigned win = __ballot_sync(FULL, (lane == (lab >> 2)) && (vl == mm));

    // sigmoid monotone: conf = sigmoid(max logit)
    float conf = __fdividef(1.0f, 1.0f + __expf(-mm));
    // searchsorted(linspace(0,1,16), conf, 'left') - 1, clipped
    int bin = __float2int_ru(conf * 15.0f) - 1;
    bin = bin < 0 ? 0 : (bin > N_BINS - 1 ? N_BINS - 1 : bin);

    if (lane == bin) {                          // lane b owns bin b
        r_cnt  += 1.0f;
        r_conf += conf;
        r_acc  += (win != 0u) ? 1.0f : 0.0f;
    }
}

__global__ void __launch_bounds__(THREADS) ece_fused_kernel(
    const float* __restrict__ logits,
    const char*  __restrict__ labels_raw,
    float* __restrict__ out,
    int n, int vec_ok, float inv_n)
{
    __shared__ float s_cnt[N_BINS], s_conf[N_BINS], s_acc[N_BINS];
    __shared__ int   s_lstride;
    __shared__ unsigned s_ticket;

    const int tid  = threadIdx.x;
    const int lane = tid & 31;

    if (tid < N_BINS) { s_cnt[tid] = 0.f; s_conf[tid] = 0.f; s_acc[tid] = 0.f; }

    // Label dtype detect: odd int32 words all zero => int64 (little-endian).
    // Either way the label value is the 32-bit word at row*lstride.
    if (tid < 32) {
        int idx = 1 + 2 * tid;
        int v = (idx < n) ? ((const int*)labels_raw)[idx] : 0;
        unsigned any = __ballot_sync(FULL, v != 0);
        if (tid == 0) s_lstride = (any == 0) ? 8 : 4;
    }
    __syncthreads();

    const int lstride = s_lstride;
    const int warp    = (int)((blockIdx.x * THREADS + tid) >> 5);
    const int nwarps  = (BLOCKS * THREADS) >> 5;

    // Per-warp register histogram: lane b (b < 15) owns bin b.
    float r_cnt = 0.0f, r_conf = 0.0f, r_acc = 0.0f;

    if (vec_ok && warp < n) {
        const int lcl = lane < 25 ? lane : 24;    // clamp: dup loads coalesce
        const float4* __restrict__ p =
            reinterpret_cast<const float4*>(logits) + (size_t)warp * 25 + lcl;
        const char* __restrict__ lp = labels_raw + (size_t)warp * lstride;
        const size_t pstride = (size_t)nwarps * 25;
        const int    lstep   = nwarps * lstride;

        const int nrows = (n - 1 - warp) / nwarps + 1;

        // ---- depth-3 pipeline: TWO rows outstanding per warp ----
        float4 va = __ldcs(p);
        int    la = *(const int*)lp;
        float4 vb; int lb;
        const float4* pn = p;
        const char*   ln = lp;
        if (nrows > 1) {
            pn += pstride; ln += lstep;
            vb = __ldcs(pn); lb = *(const int*)ln;
        }

        int it = 0;
        #pragma unroll 2
        for (; it + 2 < nrows; it++) {
            pn += pstride; ln += lstep;
            const float4 vc = __ldcs(pn);         // row it+2 in flight
            const int    lc = *(const int*)ln;

            ece_row(va, la, lane, r_cnt, r_conf, r_acc);   // row it

            va = vb; la = lb; vb = vc; lb = lc;
        }
        ece_row(va, la, lane, r_cnt, r_conf, r_acc);
        if (nrows > 1) ece_row(vb, lb, lane, r_cnt, r_conf, r_acc);
    } else if (warp < n) {
        // scalar fallback (unaligned logits base): warp-per-row
        for (int row = warp; row < n; row += nwarps) {
            float m = -CUDART_INF_F;
            float vl = 0.0f;
            int lab = *(const int*)(labels_raw + (size_t)row * lstride);
            #pragma unroll
            for (int j = 0; j < 4; j++) {
                int c = lane + j * 32;
                if (c < C_DIM) {
                    float x = logits[(size_t)row * C_DIM + c];
                    m = fmaxf(m, x);
                    if (c == lab) vl = x;
                }
            }
            unsigned maxu = __reduce_max_sync(FULL, fmap(m));
            float mm = funmap(maxu);
            unsigned win = __ballot_sync(FULL,
                (lane == (lab & 31)) && (vl == mm));
            float conf = __fdividef(1.0f, 1.0f + __expf(-mm));
            int bin = __float2int_ru(conf * 15.0f) - 1;
            bin = bin < 0 ? 0 : (bin > N_BINS - 1 ? N_BINS - 1 : bin);
            if (lane == bin) {
                r_cnt += 1.0f; r_conf += conf;
                r_acc += (win != 0u) ? 1.0f : 0.0f;
            }
        }
    }

    // warp -> block (shared) -> global
    if (lane < N_BINS && r_cnt != 0.0f) {
        atomicAdd(&s_cnt[lane],  r_cnt);
        atomicAdd(&s_conf[lane], r_conf);
        atomicAdd(&s_acc[lane],  r_acc);
    }
    __syncthreads();
    if (tid < N_BINS) {
        float c = s_cnt[tid];
        if (c != 0.0f) {
            atomicAdd(&g_cnt[tid],  c);
            atomicAdd(&g_conf[tid], (double)s_conf[tid]);
            atomicAdd(&g_accs[tid], s_acc[tid]);
        }
    }

    // ticket: last block finalizes and resets persistent state
    __threadfence();
    if (tid == 0) s_ticket = atomicAdd(&g_ctr, 1u);
    __syncthreads();
    if (s_ticket == (unsigned)(gridDim.x - 1) && tid == 0) {
        __threadfence();
        float ece = 0.0f;
        #pragma unroll
        for (int b = 0; b < N_BINS; b++) {
            float cnt = g_cnt[b];
            if (cnt > 0.0f) {
                float avg_conf = (float)g_conf[b] / cnt;
                float avg_acc  = g_accs[b] / cnt;
                ece += (avg_conf - avg_acc) * (cnt * inv_n);
            }
            g_cnt[b] = 0.0f; g_conf[b] = 0.0; g_accs[b] = 0.0f;
        }
        out[0] = ece;
        g_ctr = 0u;
        __threadfence();
    }
}

extern "C" void kernel_launch(void* const* d_in, const int* in_sizes, int n_in,
                              void* d_out, int out_size) {
    // Resolve input order by element count (logits = C_DIM x labels count).
    long long s0 = in_sizes[0], s1 = in_sizes[1];
    int logits_idx = (s0 > s1) ? 0 : 1;
    int labels_idx = 1 - logits_idx;

    const float* logits     = (const float*)d_in[logits_idx];
    const char*  labels_raw = (const char*)d_in[labels_idx];
    int n = (int)((s0 < s1) ? s0 : s1);
    float* out = (float*)d_out;

    int vec_ok = ((uintptr_t)logits & 15) == 0 ? 1 : 0;

    ece_fused_kernel<<<BLOCKS, THREADS>>>(logits, labels_raw, out, n, vec_ok,
                                          1.0f / (float)n);
}

// round 17
// speedup vs baseline: 1.7626x; 1.3768x over previous
#include <cuda_runtime.h>
#include <math_constants.h>
#include <stdint.h>

#define N_BINS  15
#define C_DIM   100
#define FULL    0xffffffffu
#define THREADS 256
#define BLOCKS  2368         // 8 blocks/SM: max warps resident

// Persistent accumulators. Zero at module load; the LAST block of every
// launch resets them after consuming -> deterministic across graph replays.
__device__ float    g_cnt[N_BINS];
__device__ double   g_conf[N_BINS];
__device__ float    g_accs[N_BINS];
__device__ unsigned g_ctr;

// Order-preserving float -> u32 map (u32 compare == float compare) + inverse.
__device__ __forceinline__ unsigned fmap(float f) {
    unsigned b = __float_as_uint(f);
    return ((int)b >= 0) ? (b | 0x80000000u) : ~b;
}
__device__ __forceinline__ float funmap(unsigned u) {
    unsigned b = (u & 0x80000000u) ? (u & 0x7fffffffu) : ~u;
    return __uint_as_float(b);
}

__global__ void __launch_bounds__(THREADS) ece_fused_kernel(
    const float* __restrict__ logits,
    const char*  __restrict__ labels_raw,
    float* __restrict__ out,
    int n, int vec_ok, float inv_n)
{
    __shared__ float s_cnt[N_BINS], s_conf[N_BINS], s_acc[N_BINS];
    __shared__ int   s_lstride;
    __shared__ unsigned s_ticket;

    const int tid  = threadIdx.x;
    const int lane = tid & 31;

    if (tid < N_BINS) { s_cnt[tid] = 0.f; s_conf[tid] = 0.f; s_acc[tid] = 0.f; }

    // Label dtype detect: odd int32 words all zero => int64 (little-endian).
    // Either way the label value is the 32-bit word at row*lstride.
    if (tid < 32) {
        int idx = 1 + 2 * tid;
        int v = (idx < n) ? ((const int*)labels_raw)[idx] : 0;
        unsigned any = __ballot_sync(FULL, v != 0);
        if (tid == 0) s_lstride = (any == 0) ? 8 : 4;
    }
    __syncthreads();

    const size_t lstride = (size_t)s_lstride;

    const int warp   = (int)((blockIdx.x * THREADS + tid) >> 5);
    const int nwarps = (BLOCKS * THREADS) >> 5;

    // Per-warp register histogram: lane b (b < 15) owns bin b.
    float r_cnt = 0.0f, r_conf = 0.0f, r_acc = 0.0f;

    if (vec_ok && warp < n) {
        const int lcl = lane < 25 ? lane : 24;    // clamp: dup loads coalesce
        const float4* __restrict__ p =
            reinterpret_cast<const float4*>(logits) + (size_t)warp * 25 + lcl;
        const char* __restrict__ lp = labels_raw + (size_t)warp * lstride;
        const size_t pstride = (size_t)nwarps * 25;
        const size_t lstep   = (size_t)nwarps * lstride;

        const int nrows = (n - 1 - warp) / nwarps + 1;

        float4 v  = *p;
        int    lab = *(const int*)lp;

        #pragma unroll 2
        for (int it = 0; it < nrows - 1; it++) {
            p  += pstride;                         // row it+1: LDG (L2 hit
            lp += lstep;                           //   thanks to prefetch)
            const float4 v2  = *p;
            const int    lab2 = *(const int*)lp;

            // L2 prefetch row it+2: no registers held, OOB is ignored.
            asm volatile("prefetch.global.L2 [%0];"
                         :: "l"((const void*)(p + pstride)));

            // ---- process current row ----
            float m = fmaxf(fmaxf(v.x, v.y), fmaxf(v.z, v.w));
            unsigned maxu = __reduce_max_sync(FULL, fmap(m));
            float mm = funmap(maxu);               // exact max logit

            int lc = lab & 3;
            float vl = (lc == 0) ? v.x : (lc == 1) ? v.y
                     : (lc == 2) ? v.z : v.w;
            unsigned win = __ballot_sync(FULL,
                (lane == (lab >> 2)) && (vl == mm));

            float conf = __fdividef(1.0f, 1.0f + __expf(-mm));
            int bin = __float2int_ru(conf * 15.0f) - 1;
            bin = bin < 0 ? 0 : (bin > N_BINS - 1 ? N_BINS - 1 : bin);
            if (lane == bin) {
                r_cnt  += 1.0f;
                r_conf += conf;
                r_acc  += (win != 0u) ? 1.0f : 0.0f;
            }

            v = v2; lab = lab2;
        }
        // ---- last row (no prefetch) ----
        {
            float m = fmaxf(fmaxf(v.x, v.y), fmaxf(v.z, v.w));
            unsigned maxu = __reduce_max_sync(FULL, fmap(m));
            float mm = funmap(maxu);
            int lc = lab & 3;
            float vl = (lc == 0) ? v.x : (lc == 1) ? v.y
                     : (lc == 2) ? v.z : v.w;
            unsigned win = __ballot_sync(FULL,
                (lane == (lab >> 2)) && (vl == mm));
            float conf = __fdividef(1.0f, 1.0f + __expf(-mm));
            int bin = __float2int_ru(conf * 15.0f) - 1;
            bin = bin < 0 ? 0 : (bin > N_BINS - 1 ? N_BINS - 1 : bin);
            if (lane == bin) {
                r_cnt  += 1.0f;
                r_conf += conf;
                r_acc  += (win != 0u) ? 1.0f : 0.0f;
            }
        }
    } else if (warp < n) {
        // scalar fallback (unaligned logits base)
        for (int row = warp; row < n; row += nwarps) {
            float m = -CUDART_INF_F;
            float vl = 0.0f;
            int lab = *(const int*)(labels_raw + (size_t)row * lstride);
            #pragma unroll
            for (int j = 0; j < 4; j++) {
                int c = lane + j * 32;
                if (c < C_DIM) {
                    float x = logits[(size_t)row * C_DIM + c];
                    m = fmaxf(m, x);
                    if (c == lab) vl = x;
                }
            }
            unsigned maxu = __reduce_max_sync(FULL, fmap(m));
            float mm = funmap(maxu);
            unsigned win = __ballot_sync(FULL,
                (lane == (lab & 31)) && (vl == mm));
            float conf = __fdividef(1.0f, 1.0f + __expf(-mm));
            int bin = __float2int_ru(conf * 15.0f) - 1;
            bin = bin < 0 ? 0 : (bin > N_BINS - 1 ? N_BINS - 1 : bin);
            if (lane == bin) {
                r_cnt += 1.0f; r_conf += conf;
                r_acc += (win != 0u) ? 1.0f : 0.0f;
            }
        }
    }

    // warp -> block (shared) -> global
    if (lane < N_BINS && r_cnt != 0.0f) {
        atomicAdd(&s_cnt[lane],  r_cnt);
        atomicAdd(&s_conf[lane], r_conf);
        atomicAdd(&s_acc[lane],  r_acc);
    }
    __syncthreads();
    if (tid < N_BINS) {
        float c = s_cnt[tid];
        if (c != 0.0f) {
            atomicAdd(&g_cnt[tid],  c);
            atomicAdd(&g_conf[tid], (double)s_conf[tid]);
            atomicAdd(&g_accs[tid], s_acc[tid]);
        }
    }

    // ticket: last block finalizes and resets persistent state
    __threadfence();
    if (tid == 0) s_ticket = atomicAdd(&g_ctr, 1u);
    __syncthreads();
    if (s_ticket == (unsigned)(gridDim.x - 1) && tid == 0) {
        __threadfence();
        float ece = 0.0f;
        #pragma unroll
        for (int b = 0; b < N_BINS; b++) {
            float cnt = g_cnt[b];
            if (cnt > 0.0f) {
                float avg_conf = (float)g_conf[b] / cnt;
                float avg_acc  = g_accs[b] / cnt;
                ece += (avg_conf - avg_acc) * (cnt * inv_n);
            }
            g_cnt[b] = 0.0f; g_conf[b] = 0.0; g_accs[b] = 0.0f;
        }
        out[0] = ece;
        g_ctr = 0u;
        __threadfence();
    }
}

extern "C" void kernel_launch(void* const* d_in, const int* in_sizes, int n_in,
                              void* d_out, int out_size) {
    // Resolve input order by element count (logits = C_DIM x labels count).
    long long s0 = in_sizes[0], s1 = in_sizes[1];
    int logits_idx = (s0 > s1) ? 0 : 1;
    int labels_idx = 1 - logits_idx;

    const float* logits     = (const float*)d_in[logits_idx];
    const char*  labels_raw = (const char*)d_in[labels_idx];
    int n = (int)((s0 < s1) ? s0 : s1);
    float* out = (float*)d_out;

    int vec_ok = ((uintptr_t)logits & 15) == 0 ? 1 : 0;

    ece_fused_kernel<<<BLOCKS, THREADS>>>(logits, labels_raw, out, n, vec_ok,
                                          1.0f / (float)n);
}